// round 4
// baseline (speedup 1.0000x reference)
#include <cuda_runtime.h>

// ---------------------------------------------------------------------------
// DeformAttnwMotion fused kernel (fp32, packed f32x2 FMA, online softmax)
//
// b=4, c=128, d=4096 (64x64), S=18 samples, OUT_C=128, 8 heads x 16 ch.
//   qp = q  @ Wq^T + bq                    (per pixel)
//   kp = kv @ Wk^T + bk ; vp = kv @ Wv^T + bv   (per pixel, per sample)
//   attn[h,s,f] = SCALE * <qp_h, kp_h(s)>
//   out = softmax_s(attn) @ vp             (online softmax, flash-style)
//   kv0_attn = softmax over s in [0,9), kv1_attn over [9,18)
//
// Output layout in d_out (float32, concatenated in reference-return order):
//   [0 , 2097152)            out      : (4,128,64,64)
//   [2097152 , 3276800)      kv0_attn : (32, 9, 4096)
//   [3276800 , 4456448)      kv1_attn : (32, 9, 4096)
// ---------------------------------------------------------------------------

typedef unsigned long long ull;

#define BB   4
#define CC   128
#define DD   4096
#define SS   18
#define OCH  128
#define NHD  8
#define HCH  16
#define FT   64            // pixels per block tile
#define SCALE_F 0.25f

// Transposed weights scratch: [m][c][oc], m = 0:Wq 1:Wk 2:Wv
__device__ float g_WT[3 * CC * OCH];

__global__ void transpose_w_kernel(const float* __restrict__ Wq,
                                   const float* __restrict__ Wk,
                                   const float* __restrict__ Wv) {
    int idx = blockIdx.x * blockDim.x + threadIdx.x;       // 0 .. 49151
    if (idx >= 3 * CC * OCH) return;
    int m   = idx >> 14;
    int rem = idx & 16383;
    int r   = rem >> 7;     // oc
    int c   = rem & 127;    // c
    const float* W = (m == 0) ? Wq : (m == 1) ? Wk : Wv;
    g_WT[m * 16384 + c * OCH + r] = W[r * CC + c];
}

// ---------------- packed f32x2 helpers ----------------
__device__ __forceinline__ ull pack2(float lo, float hi) {
    ull r;
    asm("mov.b64 %0, {%1, %2};" : "=l"(r) : "f"(lo), "f"(hi));
    return r;
}
__device__ __forceinline__ float2 unpack2(ull v) {
    float2 r;
    asm("mov.b64 {%0, %1}, %2;" : "=f"(r.x), "=f"(r.y) : "l"(v));
    return r;
}
__device__ __forceinline__ ull fma2(ull a, ull b, ull c) {
    ull d;
    asm("fma.rn.f32x2 %0, %1, %2, %3;" : "=l"(d) : "l"(a), "l"(b), "l"(c));
    return d;
}
__device__ __forceinline__ ull mul2(ull a, ull b) {
    ull d;
    asm("mul.rn.f32x2 %0, %1, %2;" : "=l"(d) : "l"(a), "l"(b));
    return d;
}
__device__ __forceinline__ void cp16(float* dst, const float* src) {
    unsigned sa = (unsigned)__cvta_generic_to_shared(dst);
    asm volatile("cp.async.cg.shared.global [%0], [%1], 16;" :: "r"(sa), "l"(src));
}

// GEMM micro-pass: ra/rb[p] += W^T[c][oc0+2p..2p+1] * X[c][fi | fi+32]
// Lanes of each f32x2 = two adjacent output channels. 16 FMA2 / c / thread.
__device__ __forceinline__ void proj_pass(const float* __restrict__ Wt,
                                          const float* __restrict__ X,
                                          int fi, int oc0,
                                          ull ra[8], ull rb[8]) {
#pragma unroll 8
    for (int c = 0; c < CC; ++c) {
        float xa = X[c * FT + fi];
        float xb = X[c * FT + fi + 32];
        ull xa2 = pack2(xa, xa);
        ull xb2 = pack2(xb, xb);
        const ull* wr = reinterpret_cast<const ull*>(Wt + c * OCH + oc0);
#pragma unroll
        for (int p = 0; p < 8; ++p) {
            ull w = wr[p];
            ra[p] = fma2(w, xa2, ra[p]);
            rb[p] = fma2(w, xb2, rb[p]);
        }
    }
}

__global__ void __launch_bounds__(256, 1)
deform_attn_kernel(const float* __restrict__ q,
                   const float* __restrict__ kv,
                   const float* __restrict__ bq,
                   const float* __restrict__ bk,
                   const float* __restrict__ bv,
                   float* __restrict__ out) {
    extern __shared__ float smem[];
    float* sWk = smem;               // 16384 floats : Wk^T [c][oc]
    float* sWv = smem + 16384;       // 16384 floats : Wq^T then Wv^T
    float* sX0 = smem + 32768;       // 8192 : q tile, then kv ping buffer
    float* sX1 = smem + 40960;       // 8192 : kv pong buffer
    float* sB  = smem + 49152;       // 384  : bq | bk | bv

    const int t   = threadIdx.x;     // 256 threads
    const int fi  = t & 31;          // pixel lane; thread owns fi and fi+32
    const int g   = t >> 5;          // head 0..7
    const int oc0 = g * HCH;
    const int b   = blockIdx.y;
    const int f0  = blockIdx.x * FT;

    // ---------------- phase 0: stage weights / q tile / first kv tile -------
    {
        const float4* gk = reinterpret_cast<const float4*>(g_WT + 16384); // WkT
        const float4* gq = reinterpret_cast<const float4*>(g_WT);         // WqT
        float4* dk = reinterpret_cast<float4*>(sWk);
        float4* dq = reinterpret_cast<float4*>(sWv);
#pragma unroll
        for (int i = 0; i < 16; ++i) {
            int idx = t + i * 256;
            dk[idx] = gk[idx];
            dq[idx] = gq[idx];
        }
#pragma unroll
        for (int i = 0; i < 8; ++i) {
            int idx = t + i * 256;
            int c = idx >> 4, f4 = idx & 15;
            reinterpret_cast<float4*>(sX0 + c * FT)[f4] =
                reinterpret_cast<const float4*>(q + ((size_t)(b * CC + c)) * DD + f0)[f4];
        }
        if (t < 128) {
            sB[t]       = bq[t];
            sB[128 + t] = bk[t];
            sB[256 + t] = bv[t];
        }
#pragma unroll
        for (int i = 0; i < 8; ++i) {
            int idx = t + i * 256;
            int c = idx >> 4, f4 = idx & 15;
            cp16(sX1 + c * FT + f4 * 4,
                 kv + (((size_t)(b * CC + c)) * SS + 0) * DD + f0 + f4 * 4);
        }
        asm volatile("cp.async.commit_group;" ::: "memory");
    }
    __syncthreads();

    // ---------------- q projection (sWv currently holds Wq^T) ---------------
    ull qpa[8], qpb[8];
#pragma unroll
    for (int p = 0; p < 8; ++p) {
        ull bb = pack2(sB[oc0 + 2 * p], sB[oc0 + 2 * p + 1]);
        qpa[p] = bb; qpb[p] = bb;
    }
    proj_pass(sWv, sX0, fi, oc0, qpa, qpb);
    __syncthreads();                 // done reading Wq^T and q tile

    {   // overwrite with Wv^T
        const float4* gv = reinterpret_cast<const float4*>(g_WT + 32768);
        float4* dv = reinterpret_cast<float4*>(sWv);
#pragma unroll
        for (int i = 0; i < 16; ++i) {
            int idx = t + i * 256;
            dv[idx] = gv[idx];
        }
    }
    __syncthreads();

    // ---------------- online-softmax state -----------------------------------
    const float NEG = -1e30f;
    float m_a = NEG, Z_a = 0.f, m_b = NEG, Z_b = 0.f;       // full softmax (out)
    float m0a = NEG, Z0a = 0.f, m1a = NEG, Z1a = 0.f;       // half trackers px a
    float m0b = NEG, Z0b = 0.f, m1b = NEG, Z1b = 0.f;       // half trackers px b
    ull acc_a[8], acc_b[8];
#pragma unroll
    for (int p = 0; p < 8; ++p) { acc_a[p] = 0ull; acc_b[p] = 0ull; }

    float* attn0 = out + (size_t)BB * OCH * DD;             // 2097152
    float* attn1 = attn0 + (size_t)BB * NHD * 9 * DD;       // +1179648

    // ---------------- main sample loop ---------------------------------------
    for (int s = 0; s < SS; ++s) {
        float* cur = (s & 1) ? sX0 : sX1;
        float* nxt = (s & 1) ? sX1 : sX0;
        if (s < SS - 1) {
#pragma unroll
            for (int i = 0; i < 8; ++i) {
                int idx = t + i * 256;
                int c = idx >> 4, f4 = idx & 15;
                cp16(nxt + c * FT + f4 * 4,
                     kv + (((size_t)(b * CC + c)) * SS + (s + 1)) * DD + f0 + f4 * 4);
            }
            asm volatile("cp.async.commit_group;" ::: "memory");
            asm volatile("cp.async.wait_group 1;" ::: "memory");
        } else {
            asm volatile("cp.async.wait_group 0;" ::: "memory");
        }
        __syncthreads();

        // ---- K projection ----
        ull ka[8], kb[8];
#pragma unroll
        for (int p = 0; p < 8; ++p) {
            ull bbk = pack2(sB[128 + oc0 + 2 * p], sB[128 + oc0 + 2 * p + 1]);
            ka[p] = bbk; kb[p] = bbk;
        }
        proj_pass(sWk, cur, fi, oc0, ka, kb);

        // ---- logits (dot over the 16 head channels, both lanes) ----
        ull da = 0ull, db = 0ull;
#pragma unroll
        for (int p = 0; p < 8; ++p) {
            da = fma2(qpa[p], ka[p], da);
            db = fma2(qpb[p], kb[p], db);
        }
        float2 dau = unpack2(da), dbu = unpack2(db);
        float a_a = (dau.x + dau.y) * SCALE_F;
        float a_b = (dbu.x + dbu.y) * SCALE_F;

        // stage raw logits into the attn output region (same thread re-reads)
        {
            float* base = (s < 9) ? attn0 : attn1;
            int ss = (s < 9) ? s : s - 9;
            size_t off = ((size_t)(b * NHD + g) * 9 + ss) * DD + f0 + fi;
            base[off]      = a_a;
            base[off + 32] = a_b;
        }

        // ---- per-half online (m, Z) ----
        if (s < 9) {
            float nm = fmaxf(m0a, a_a);
            Z0a = Z0a * __expf(m0a - nm) + __expf(a_a - nm); m0a = nm;
            nm = fmaxf(m0b, a_b);
            Z0b = Z0b * __expf(m0b - nm) + __expf(a_b - nm); m0b = nm;
        } else {
            float nm = fmaxf(m1a, a_a);
            Z1a = Z1a * __expf(m1a - nm) + __expf(a_a - nm); m1a = nm;
            nm = fmaxf(m1b, a_b);
            Z1b = Z1b * __expf(m1b - nm) + __expf(a_b - nm); m1b = nm;
        }

        // ---- full online softmax rescale factors ----
        float nma = fmaxf(m_a, a_a);
        float caf = __expf(m_a - nma), paf = __expf(a_a - nma);
        Z_a = Z_a * caf + paf; m_a = nma;
        float nmb = fmaxf(m_b, a_b);
        float cbf = __expf(m_b - nmb), pbf = __expf(a_b - nmb);
        Z_b = Z_b * cbf + pbf; m_b = nmb;

        ull ca2 = pack2(caf, caf), pa2 = pack2(paf, paf);
        ull cb2 = pack2(cbf, cbf), pb2 = pack2(pbf, pbf);

        // ---- V projection (reuse ka/kb registers as vp) ----
#pragma unroll
        for (int p = 0; p < 8; ++p) {
            ull bbv = pack2(sB[256 + oc0 + 2 * p], sB[256 + oc0 + 2 * p + 1]);
            ka[p] = bbv; kb[p] = bbv;
        }
        proj_pass(sWv, cur, fi, oc0, ka, kb);

        // acc = acc*corr + vp*p   (packed, both channels)
#pragma unroll
        for (int p = 0; p < 8; ++p) {
            acc_a[p] = fma2(acc_a[p], ca2, mul2(ka[p], pa2));
            acc_b[p] = fma2(acc_b[p], cb2, mul2(kb[p], pb2));
        }
        __syncthreads();    // all readers of 'cur' done before it is refilled
    }

    // ---------------- epilogue: out = acc / Z -------------------------------
    {
        float ia = 1.f / Z_a, ib = 1.f / Z_b;
#pragma unroll
        for (int p = 0; p < 8; ++p) {
            float2 oa = unpack2(acc_a[p]);
            float2 ob = unpack2(acc_b[p]);
            size_t r0 = ((size_t)(b * OCH + oc0 + 2 * p)) * DD + f0 + fi;
            size_t r1 = r0 + DD;
            out[r0]      = oa.x * ia;
            out[r1]      = oa.y * ia;
            out[r0 + 32] = ob.x * ib;
            out[r1 + 32] = ob.y * ib;
        }
    }

    // ---------------- epilogue: half softmaxes over staged logits -----------
    {
        float i0a = 1.f / Z0a, i1a = 1.f / Z1a;
        float i0b = 1.f / Z0b, i1b = 1.f / Z1b;
        size_t baseoff = ((size_t)(b * NHD + g) * 9) * DD + f0 + fi;
#pragma unroll
        for (int ss = 0; ss < 9; ++ss) {
            size_t off = baseoff + (size_t)ss * DD;
            float la  = attn0[off], lb  = attn0[off + 32];
            attn0[off]      = __expf(la  - m0a) * i0a;
            attn0[off + 32] = __expf(lb  - m0b) * i0b;
            float la1 = attn1[off], lb1 = attn1[off + 32];
            attn1[off]      = __expf(la1 - m1a) * i1a;
            attn1[off + 32] = __expf(lb1 - m1b) * i1b;
        }
    }
}

// ---------------------------------------------------------------------------
extern "C" void kernel_launch(void* const* d_in, const int* in_sizes, int n_in,
                              void* d_out, int out_size) {
    const float* q  = (const float*)d_in[0];
    const float* kv = (const float*)d_in[1];
    const float* Wq = (const float*)d_in[2];
    const float* bq = (const float*)d_in[3];
    const float* Wk = (const float*)d_in[4];
    const float* bk = (const float*)d_in[5];
    const float* Wv = (const float*)d_in[6];
    const float* bv = (const float*)d_in[7];
    float* out = (float*)d_out;

    cudaFuncSetAttribute(deform_attn_kernel,
                         cudaFuncAttributeMaxDynamicSharedMemorySize, 198144);

    transpose_w_kernel<<<192, 256>>>(Wq, Wk, Wv);
    deform_attn_kernel<<<dim3(DD / FT, BB), 256, 198144>>>(q, kv, bq, bk, bv, out);
}

// round 5
// speedup vs baseline: 1.0086x; 1.0086x over previous
#include <cuda_runtime.h>

// ---------------------------------------------------------------------------
// DeformAttnwMotion fused kernel, round 5
//   R4 -> R5 changes:
//   1. Weight smem loads via LDS.128 (ulonglong2) -> smem crossbar no longer
//      the binding pipe (48 vs 64 fma cycles per c per SM).
//   2. grid = 128 persistent-ish blocks x 2 tile-units -> exactly 1 wave,
//      no 256/148 quantization penalty; Wk staged once per block.
//
// b=4, c=128, d=4096 (64x64), S=18 samples, OUT_C=128, 8 heads x 16 ch.
// Output layout in d_out (float32):
//   [0 , 2097152)            out      : (4,128,64,64)
//   [2097152 , 3276800)      kv0_attn : (32, 9, 4096)
//   [3276800 , 4456448)      kv1_attn : (32, 9, 4096)
// ---------------------------------------------------------------------------

typedef unsigned long long ull;

#define BB   4
#define CC   128
#define DD   4096
#define SS   18
#define OCH  128
#define NHD  8
#define HCH  16
#define FT   64            // pixels per tile-unit
#define UNITS_PER_BLOCK 2
#define GRID_X 128         // 256 units / 2
#define SCALE_F 0.25f

// Transposed weights scratch: [m][c][oc], m = 0:Wq 1:Wk 2:Wv
__device__ float g_WT[3 * CC * OCH];

__global__ void transpose_w_kernel(const float* __restrict__ Wq,
                                   const float* __restrict__ Wk,
                                   const float* __restrict__ Wv) {
    int idx = blockIdx.x * blockDim.x + threadIdx.x;       // 0 .. 49151
    if (idx >= 3 * CC * OCH) return;
    int m   = idx >> 14;
    int rem = idx & 16383;
    int r   = rem >> 7;     // oc
    int c   = rem & 127;    // c
    const float* W = (m == 0) ? Wq : (m == 1) ? Wk : Wv;
    g_WT[m * 16384 + c * OCH + r] = W[r * CC + c];
}

// ---------------- packed f32x2 helpers ----------------
__device__ __forceinline__ ull pack2(float lo, float hi) {
    ull r;
    asm("mov.b64 %0, {%1, %2};" : "=l"(r) : "f"(lo), "f"(hi));
    return r;
}
__device__ __forceinline__ float2 unpack2(ull v) {
    float2 r;
    asm("mov.b64 {%0, %1}, %2;" : "=f"(r.x), "=f"(r.y) : "l"(v));
    return r;
}
__device__ __forceinline__ ull fma2(ull a, ull b, ull c) {
    ull d;
    asm("fma.rn.f32x2 %0, %1, %2, %3;" : "=l"(d) : "l"(a), "l"(b), "l"(c));
    return d;
}
__device__ __forceinline__ ull mul2(ull a, ull b) {
    ull d;
    asm("mul.rn.f32x2 %0, %1, %2;" : "=l"(d) : "l"(a), "l"(b));
    return d;
}
__device__ __forceinline__ void cp16(float* dst, const float* src) {
    unsigned sa = (unsigned)__cvta_generic_to_shared(dst);
    asm volatile("cp.async.cg.shared.global [%0], [%1], 16;" :: "r"(sa), "l"(src));
}

// GEMM micro-pass: ra/rb[p] += W^T[c][oc0+2p..2p+1] * X[c][fi | fi+32]
// Weights read as LDS.128 (2 packed f32x2 per load). 16 FMA2 / c / thread.
__device__ __forceinline__ void proj_pass(const float* __restrict__ Wt,
                                          const float* __restrict__ X,
                                          int fi, int oc0,
                                          ull ra[8], ull rb[8]) {
#pragma unroll 8
    for (int c = 0; c < CC; ++c) {
        float xa = X[c * FT + fi];
        float xb = X[c * FT + fi + 32];
        ull xa2 = pack2(xa, xa);
        ull xb2 = pack2(xb, xb);
        const ulonglong2* wr =
            reinterpret_cast<const ulonglong2*>(Wt + c * OCH + oc0);
#pragma unroll
        for (int p = 0; p < 4; ++p) {
            ulonglong2 w = wr[p];               // LDS.128: 4 weight floats
            ra[2 * p]     = fma2(w.x, xa2, ra[2 * p]);
            rb[2 * p]     = fma2(w.x, xb2, rb[2 * p]);
            ra[2 * p + 1] = fma2(w.y, xa2, ra[2 * p + 1]);
            rb[2 * p + 1] = fma2(w.y, xb2, rb[2 * p + 1]);
        }
    }
}

__global__ void __launch_bounds__(256, 1)
deform_attn_kernel(const float* __restrict__ q,
                   const float* __restrict__ kv,
                   const float* __restrict__ bq,
                   const float* __restrict__ bk,
                   const float* __restrict__ bv,
                   float* __restrict__ out) {
    extern __shared__ float smem[];
    float* sWk = smem;               // 16384 floats : Wk^T [c][oc], whole block life
    float* sWv = smem + 16384;       // 16384 floats : Wq^T then Wv^T (per tile)
    float* sX0 = smem + 32768;       // 8192 : q tile, then kv ping buffer
    float* sX1 = smem + 40960;       // 8192 : kv pong buffer
    float* sB  = smem + 49152;       // 384  : bq | bk | bv

    const int t   = threadIdx.x;     // 256 threads
    const int fi  = t & 31;          // pixel lane; thread owns fi and fi+32
    const int g   = t >> 5;          // head 0..7
    const int oc0 = g * HCH;

    float* attn0 = out + (size_t)BB * OCH * DD;             // 2097152
    float* attn1 = attn0 + (size_t)BB * NHD * 9 * DD;       // +1179648

    // ------------- once per block: Wk^T + biases -----------------------------
    {
        const float4* gk = reinterpret_cast<const float4*>(g_WT + 16384); // WkT
        float4* dk = reinterpret_cast<float4*>(sWk);
#pragma unroll
        for (int i = 0; i < 16; ++i) {
            int idx = t + i * 256;
            dk[idx] = gk[idx];
        }
        if (t < 128) {
            sB[t]       = bq[t];
            sB[128 + t] = bk[t];
            sB[256 + t] = bv[t];
        }
    }

    // ------------- tile-unit loop (2 units, one wave, perfectly balanced) ----
    for (int it = 0; it < UNITS_PER_BLOCK; ++it) {
        const int unit = blockIdx.x + it * GRID_X;   // 0..255
        const int b    = unit >> 6;                  // batch
        const int f0   = (unit & 63) * FT;           // pixel-tile origin

        // phase 0: Wq^T -> sWv, q tile -> sX0, kv(s=0) -> sX1 (async)
        {
            const float4* gq = reinterpret_cast<const float4*>(g_WT);   // WqT
            float4* dq = reinterpret_cast<float4*>(sWv);
#pragma unroll
            for (int i = 0; i < 16; ++i) {
                int idx = t + i * 256;
                dq[idx] = gq[idx];
            }
#pragma unroll
            for (int i = 0; i < 8; ++i) {
                int idx = t + i * 256;
                int c = idx >> 4, f4 = idx & 15;
                reinterpret_cast<float4*>(sX0 + c * FT)[f4] =
                    reinterpret_cast<const float4*>(
                        q + ((size_t)(b * CC + c)) * DD + f0)[f4];
            }
#pragma unroll
            for (int i = 0; i < 8; ++i) {
                int idx = t + i * 256;
                int c = idx >> 4, f4 = idx & 15;
                cp16(sX1 + c * FT + f4 * 4,
                     kv + (((size_t)(b * CC + c)) * SS + 0) * DD + f0 + f4 * 4);
            }
            asm volatile("cp.async.commit_group;" ::: "memory");
        }
        __syncthreads();

        // q projection (sWv holds Wq^T)
        ull qpa[8], qpb[8];
#pragma unroll
        for (int p = 0; p < 8; ++p) {
            ull bb = pack2(sB[oc0 + 2 * p], sB[oc0 + 2 * p + 1]);
            qpa[p] = bb; qpb[p] = bb;
        }
        proj_pass(sWv, sX0, fi, oc0, qpa, qpb);
        __syncthreads();                 // done reading Wq^T and q tile

        {   // overwrite with Wv^T
            const float4* gv = reinterpret_cast<const float4*>(g_WT + 32768);
            float4* dv = reinterpret_cast<float4*>(sWv);
#pragma unroll
            for (int i = 0; i < 16; ++i) {
                int idx = t + i * 256;
                dv[idx] = gv[idx];
            }
        }
        __syncthreads();

        // online-softmax state
        const float NEG = -1e30f;
        float m_a = NEG, Z_a = 0.f, m_b = NEG, Z_b = 0.f;   // full softmax
        float m0a = NEG, Z0a = 0.f, m1a = NEG, Z1a = 0.f;   // half trackers px a
        float m0b = NEG, Z0b = 0.f, m1b = NEG, Z1b = 0.f;   // half trackers px b
        ull acc_a[8], acc_b[8];
#pragma unroll
        for (int p = 0; p < 8; ++p) { acc_a[p] = 0ull; acc_b[p] = 0ull; }

        // main sample loop
        for (int s = 0; s < SS; ++s) {
            float* cur = (s & 1) ? sX0 : sX1;
            float* nxt = (s & 1) ? sX1 : sX0;
            if (s < SS - 1) {
#pragma unroll
                for (int i = 0; i < 8; ++i) {
                    int idx = t + i * 256;
                    int c = idx >> 4, f4 = idx & 15;
                    cp16(nxt + c * FT + f4 * 4,
                         kv + (((size_t)(b * CC + c)) * SS + (s + 1)) * DD
                            + f0 + f4 * 4);
                }
                asm volatile("cp.async.commit_group;" ::: "memory");
                asm volatile("cp.async.wait_group 1;" ::: "memory");
            } else {
                asm volatile("cp.async.wait_group 0;" ::: "memory");
            }
            __syncthreads();

            // ---- K projection ----
            ull ka[8], kb[8];
#pragma unroll
            for (int p = 0; p < 8; ++p) {
                ull bbk = pack2(sB[128 + oc0 + 2 * p], sB[128 + oc0 + 2 * p + 1]);
                ka[p] = bbk; kb[p] = bbk;
            }
            proj_pass(sWk, cur, fi, oc0, ka, kb);

            // ---- logits ----
            ull da = 0ull, db = 0ull;
#pragma unroll
            for (int p = 0; p < 8; ++p) {
                da = fma2(qpa[p], ka[p], da);
                db = fma2(qpb[p], kb[p], db);
            }
            float2 dau = unpack2(da), dbu = unpack2(db);
            float a_a = (dau.x + dau.y) * SCALE_F;
            float a_b = (dbu.x + dbu.y) * SCALE_F;

            // stage raw logits into the attn output region (same thread re-reads)
            {
                float* base = (s < 9) ? attn0 : attn1;
                int ss = (s < 9) ? s : s - 9;
                size_t off = ((size_t)(b * NHD + g) * 9 + ss) * DD + f0 + fi;
                base[off]      = a_a;
                base[off + 32] = a_b;
            }

            // ---- per-half online (m, Z) ----
            if (s < 9) {
                float nm = fmaxf(m0a, a_a);
                Z0a = Z0a * __expf(m0a - nm) + __expf(a_a - nm); m0a = nm;
                nm = fmaxf(m0b, a_b);
                Z0b = Z0b * __expf(m0b - nm) + __expf(a_b - nm); m0b = nm;
            } else {
                float nm = fmaxf(m1a, a_a);
                Z1a = Z1a * __expf(m1a - nm) + __expf(a_a - nm); m1a = nm;
                nm = fmaxf(m1b, a_b);
                Z1b = Z1b * __expf(m1b - nm) + __expf(a_b - nm); m1b = nm;
            }

            // ---- full online softmax rescale ----
            float nma = fmaxf(m_a, a_a);
            float caf = __expf(m_a - nma), paf = __expf(a_a - nma);
            Z_a = Z_a * caf + paf; m_a = nma;
            float nmb = fmaxf(m_b, a_b);
            float cbf = __expf(m_b - nmb), pbf = __expf(a_b - nmb);
            Z_b = Z_b * cbf + pbf; m_b = nmb;

            ull ca2 = pack2(caf, caf), pa2 = pack2(paf, paf);
            ull cb2 = pack2(cbf, cbf), pb2 = pack2(pbf, pbf);

            // ---- V projection (reuse ka/kb as vp) ----
#pragma unroll
            for (int p = 0; p < 8; ++p) {
                ull bbv = pack2(sB[256 + oc0 + 2 * p], sB[256 + oc0 + 2 * p + 1]);
                ka[p] = bbv; kb[p] = bbv;
            }
            proj_pass(sWv, cur, fi, oc0, ka, kb);

            // acc = acc*corr + vp*p
#pragma unroll
            for (int p = 0; p < 8; ++p) {
                acc_a[p] = fma2(acc_a[p], ca2, mul2(ka[p], pa2));
                acc_b[p] = fma2(acc_b[p], cb2, mul2(kb[p], pb2));
            }
            __syncthreads();    // all readers of 'cur' done before refill
        }

        // epilogue: out = acc / Z
        {
            float ia = 1.f / Z_a, ib = 1.f / Z_b;
#pragma unroll
            for (int p = 0; p < 8; ++p) {
                float2 oa = unpack2(acc_a[p]);
                float2 ob = unpack2(acc_b[p]);
                size_t r0 = ((size_t)(b * OCH + oc0 + 2 * p)) * DD + f0 + fi;
                size_t r1 = r0 + DD;
                out[r0]      = oa.x * ia;
                out[r1]      = oa.y * ia;
                out[r0 + 32] = ob.x * ib;
                out[r1 + 32] = ob.y * ib;
            }
        }

        // epilogue: half softmaxes over staged logits
        {
            float i0a = 1.f / Z0a, i1a = 1.f / Z1a;
            float i0b = 1.f / Z0b, i1b = 1.f / Z1b;
            size_t baseoff = ((size_t)(b * NHD + g) * 9) * DD + f0 + fi;
#pragma unroll
            for (int ss = 0; ss < 9; ++ss) {
                size_t off = baseoff + (size_t)ss * DD;
                float la  = attn0[off], lb  = attn0[off + 32];
                attn0[off]      = __expf(la  - m0a) * i0a;
                attn0[off + 32] = __expf(lb  - m0b) * i0b;
                float la1 = attn1[off], lb1 = attn1[off + 32];
                attn1[off]      = __expf(la1 - m1a) * i1a;
                attn1[off + 32] = __expf(lb1 - m1b) * i1b;
            }
        }
        __syncthreads();   // tile-unit boundary: smem safe to restage
    }
}

// ---------------------------------------------------------------------------
extern "C" void kernel_launch(void* const* d_in, const int* in_sizes, int n_in,
                              void* d_out, int out_size) {
    const float* q  = (const float*)d_in[0];
    const float* kv = (const float*)d_in[1];
    const float* Wq = (const float*)d_in[2];
    const float* bq = (const float*)d_in[3];
    const float* Wk = (const float*)d_in[4];
    const float* bk = (const float*)d_in[5];
    const float* Wv = (const float*)d_in[6];
    const float* bv = (const float*)d_in[7];
    float* out = (float*)d_out;

    cudaFuncSetAttribute(deform_attn_kernel,
                         cudaFuncAttributeMaxDynamicSharedMemorySize, 198144);

    transpose_w_kernel<<<192, 256>>>(Wq, Wk, Wv);
    deform_attn_kernel<<<dim3(GRID_X), 256, 198144>>>(q, kv, bq, bk, bv, out);
}